// round 4
// baseline (speedup 1.0000x reference)
#include <cuda_runtime.h>
#include <math.h>

// Problem shape (fixed by reference setup_inputs)
#define BB 8
#define DD 64
#define HW (256 * 512)        // 131072
#define PIXELS (BB * HW)      // 1048576
#define TPB 128
#define NBLOCKS (PIXELS / 4 / TPB)   // 2048

#define E2      7.3890560989306495f     // e^2
#define INV_E2  0.1353352832366127f     // e^-2
#define E_P63   2.2937831594696098e27f  // e^63
#define E_M63   4.3596100000630809e-28f // e^-63

// Allocation-free scratch
__device__ float        g_partial[NBLOCKS];
__device__ int          g_pcnt[NBLOCKS];
__device__ unsigned int g_done;      // zero-init; reset by last block each replay

// entropy = log(sum_d exp(x_d)) - (sum_d w_d*x_d)/(sum_d w_d)
// w_d = e^{-|gt-2d|} = min(e^{2d-gt}, e^{gt-2d}) = min(t_lo*c1, t_hi*c2)
//   t_lo = e^{2d-63}, t_hi = e^{63-2d}  (uniform, carried multiplicatively)
//   c1 = e^{63-gt},   c2 = e^{gt-63}   (per-pixel, hoisted)
// One side may overflow to +inf; FMNMX picks the finite correct side.
// gt = inf  ->  c1 = 0  ->  min(0, inf) = 0  (masked), and known <=> c1 != 0.
__global__ void __launch_bounds__(TPB)
sce_fused_kernel(const float* __restrict__ sim, const float* __restrict__ gt,
                 float* __restrict__ out) {
    const int tid = blockIdx.x * TPB + threadIdx.x;
    const int p   = tid * 4;
    const int b   = p / HW;
    const int rem = p - b * HW;

    const float4* simv = (const float4*)(sim + (size_t)b * DD * HW + rem);

    const float4 g = __ldg((const float4*)(gt + p));
    float c1[4], c2[4], se[4], spt[4], sptx[4];
    {
        const float gtv[4] = {g.x, g.y, g.z, g.w};
        #pragma unroll
        for (int j = 0; j < 4; ++j) {
            se[j] = 0.f; spt[j] = 0.f; sptx[j] = 0.f;
            c1[j] = __expf(63.0f - gtv[j]);   // 0 when gt = inf
            c2[j] = __expf(gtv[j] - 63.0f);
        }
    }

    float t_lo = E_M63;   // e^{2d-63}
    float t_hi = E_P63;   // e^{63-2d}

    #pragma unroll 8
    for (int d = 0; d < DD; ++d) {
        const float4 x = __ldcs(&simv[(size_t)d * (HW / 4)]);
        const float xs[4] = {x.x, x.y, x.z, x.w};
        #pragma unroll
        for (int j = 0; j < 4; ++j) {
            const float xx = xs[j];
            se[j] += __expf(xx);
            const float w = fminf(t_lo * c1[j], t_hi * c2[j]);
            spt[j]  += w;
            sptx[j] += w * xx;
        }
        t_lo *= E2;
        t_hi *= INV_E2;
    }

    float local = 0.f;
    int   cnt   = 0;
    #pragma unroll
    for (int j = 0; j < 4; ++j) {
        if (c1[j] != 0.0f) {   // known ground truth
            local += __logf(se[j]) - __fdividef(sptx[j], spt[j]);
            cnt   += 1;
        }
    }

    // Block reduce (4 warps)
    #pragma unroll
    for (int o = 16; o > 0; o >>= 1) {
        local += __shfl_down_sync(0xffffffffu, local, o);
        cnt   += __shfl_down_sync(0xffffffffu, cnt, o);
    }
    __shared__ float ssum[4];
    __shared__ int   scnt[4];
    __shared__ bool  isLast;
    const int lane = threadIdx.x & 31;
    const int wid  = threadIdx.x >> 5;
    if (lane == 0) { ssum[wid] = local; scnt[wid] = cnt; }
    __syncthreads();
    if (wid == 0) {
        local = (lane < 4) ? ssum[lane] : 0.f;
        cnt   = (lane < 4) ? scnt[lane] : 0;
        #pragma unroll
        for (int o = 2; o > 0; o >>= 1) {
            local += __shfl_down_sync(0xffffffffu, local, o);
            cnt   += __shfl_down_sync(0xffffffffu, cnt, o);
        }
        if (lane == 0) {
            g_partial[blockIdx.x] = local;
            g_pcnt[blockIdx.x]    = cnt;
            __threadfence();
            unsigned int prev = atomicAdd(&g_done, 1u);
            isLast = (prev == (unsigned int)(gridDim.x - 1));
        }
    }
    __syncthreads();

    // Last finished block reduces all partials
    if (isLast) {
        __threadfence();
        const volatile float* vp = g_partial;
        const volatile int*   vc = g_pcnt;
        float s = 0.f;
        int   c = 0;
        #pragma unroll
        for (int k = 0; k < NBLOCKS / TPB; ++k) {
            s += vp[threadIdx.x + k * TPB];
            c += vc[threadIdx.x + k * TPB];
        }
        #pragma unroll
        for (int o = 16; o > 0; o >>= 1) {
            s += __shfl_down_sync(0xffffffffu, s, o);
            c += __shfl_down_sync(0xffffffffu, c, o);
        }
        if (lane == 0) { ssum[wid] = s; scnt[wid] = c; }
        __syncthreads();
        if (wid == 0) {
            s = (lane < 4) ? ssum[lane] : 0.f;
            c = (lane < 4) ? scnt[lane] : 0;
            #pragma unroll
            for (int o = 2; o > 0; o >>= 1) {
                s += __shfl_down_sync(0xffffffffu, s, o);
                c += __shfl_down_sync(0xffffffffu, c, o);
            }
            if (lane == 0) {
                out[0] = s / (float)c;
                g_done = 0;   // reset for next graph replay
            }
        }
    }
}

extern "C" void kernel_launch(void* const* d_in, const int* in_sizes, int n_in,
                              void* d_out, int out_size) {
    const float* sim = (const float*)d_in[0];
    const float* gt  = (const float*)d_in[1];
    float* out       = (float*)d_out;

    sce_fused_kernel<<<NBLOCKS, TPB>>>(sim, gt, out);
}

// round 6
// speedup vs baseline: 1.1578x; 1.1578x over previous
#include <cuda_runtime.h>
#include <cuda_pipeline.h>
#include <math.h>

// Problem shape (fixed by reference setup_inputs)
#define BB 8
#define DD 64
#define HW (256 * 512)        // 131072
#define PIXELS (BB * HW)      // 1048576
#define TPB 256
#define NBLOCKS (PIXELS / 4 / TPB)   // 1024

#define STAGES 8
#define DIST   7              // prefetch distance (< STAGES)

#define E2      7.3890560989306495f     // e^2
#define INV_E2  0.1353352832366127f     // e^-2
#define E_P63   2.2937831594696098e27f  // e^63
#define E_M63   4.3596100000630809e-28f // e^-63

// Allocation-free scratch
__device__ float        g_partial[NBLOCKS];
__device__ int          g_pcnt[NBLOCKS];
__device__ unsigned int g_done;      // zero-init; reset by last block each replay

// entropy = log(sum_d exp(x_d)) - (sum_d w_d*x_d)/(sum_d w_d)
// w_d = e^{-|gt-2d|} = min(t_lo*c1, t_hi*c2); gt=inf -> c1=0 -> w=0 (masked).
__global__ void __launch_bounds__(TPB)
sce_fused_kernel(const float* __restrict__ sim, const float* __restrict__ gt,
                 float* __restrict__ out) {
    __shared__ float4 buf[STAGES][TPB];    // 32 KB staging

    const int tid = blockIdx.x * TPB + threadIdx.x;
    const int p   = tid * 4;
    const int b   = p / HW;
    const int rem = p - b * HW;

    const float4* simv = (const float4*)(sim + (size_t)b * DD * HW + rem);

    const float4 g = *(const float4*)(gt + p);
    float c1[4], c2[4], se[4], spt[4], sptx[4];
    {
        const float gtv[4] = {g.x, g.y, g.z, g.w};
        #pragma unroll
        for (int j = 0; j < 4; ++j) {
            se[j] = 0.f; spt[j] = 0.f; sptx[j] = 0.f;
            c1[j] = __expf(63.0f - gtv[j]);   // 0 when gt = inf
            c2[j] = __expf(gtv[j] - 63.0f);
        }
    }

    // Prologue: prefetch d = 0..DIST-1, one commit-group per stage
    #pragma unroll
    for (int d = 0; d < DIST; ++d) {
        __pipeline_memcpy_async(&buf[d][threadIdx.x],
                                &simv[(size_t)d * (HW / 4)], 16);
        __pipeline_commit();
    }

    float t_lo = E_M63;   // e^{2d-63}
    float t_hi = E_P63;   // e^{63-2d}

    #pragma unroll 4
    for (int d = 0; d < DD; ++d) {
        __pipeline_wait_prior(DIST - 1);            // group d complete
        const float4 x = buf[d & (STAGES - 1)][threadIdx.x];

        // Prefetch d+DIST into the buffer read last iteration (long drained)
        const int dn = d + DIST;
        if (dn < DD)
            __pipeline_memcpy_async(&buf[dn & (STAGES - 1)][threadIdx.x],
                                    &simv[(size_t)dn * (HW / 4)], 16);
        __pipeline_commit();                        // keep group count aligned

        const float xs[4] = {x.x, x.y, x.z, x.w};
        #pragma unroll
        for (int j = 0; j < 4; ++j) {
            const float xx = xs[j];
            se[j] += __expf(xx);
            const float w = fminf(t_lo * c1[j], t_hi * c2[j]);
            spt[j]  += w;
            sptx[j] += w * xx;
        }
        t_lo *= E2;
        t_hi *= INV_E2;
    }

    float local = 0.f;
    int   cnt   = 0;
    #pragma unroll
    for (int j = 0; j < 4; ++j) {
        if (c1[j] != 0.0f) {   // known ground truth
            local += __logf(se[j]) - __fdividef(sptx[j], spt[j]);
            cnt   += 1;
        }
    }

    // Block reduce (8 warps)
    #pragma unroll
    for (int o = 16; o > 0; o >>= 1) {
        local += __shfl_down_sync(0xffffffffu, local, o);
        cnt   += __shfl_down_sync(0xffffffffu, cnt, o);
    }
    __shared__ float ssum[8];
    __shared__ int   scnt[8];
    __shared__ bool  isLast;
    const int lane = threadIdx.x & 31;
    const int wid  = threadIdx.x >> 5;
    if (lane == 0) { ssum[wid] = local; scnt[wid] = cnt; }
    __syncthreads();
    if (wid == 0) {
        local = (lane < 8) ? ssum[lane] : 0.f;
        cnt   = (lane < 8) ? scnt[lane] : 0;
        #pragma unroll
        for (int o = 4; o > 0; o >>= 1) {
            local += __shfl_down_sync(0xffffffffu, local, o);
            cnt   += __shfl_down_sync(0xffffffffu, cnt, o);
        }
        if (lane == 0) {
            g_partial[blockIdx.x] = local;
            g_pcnt[blockIdx.x]    = cnt;
            __threadfence();
            unsigned int prev = atomicAdd(&g_done, 1u);
            isLast = (prev == (unsigned int)(gridDim.x - 1));
        }
    }
    __syncthreads();

    // Last finished block reduces all partials
    if (isLast) {
        __threadfence();
        const volatile float* vp = g_partial;
        const volatile int*   vc = g_pcnt;
        float s = 0.f;
        int   c = 0;
        #pragma unroll
        for (int k = 0; k < NBLOCKS / TPB; ++k) {
            s += vp[threadIdx.x + k * TPB];
            c += vc[threadIdx.x + k * TPB];
        }
        #pragma unroll
        for (int o = 16; o > 0; o >>= 1) {
            s += __shfl_down_sync(0xffffffffu, s, o);
            c += __shfl_down_sync(0xffffffffu, c, o);
        }
        if (lane == 0) { ssum[wid] = s; scnt[wid] = c; }
        __syncthreads();
        if (wid == 0) {
            s = (lane < 8) ? ssum[lane] : 0.f;
            c = (lane < 8) ? scnt[lane] : 0;
            #pragma unroll
            for (int o = 4; o > 0; o >>= 1) {
                s += __shfl_down_sync(0xffffffffu, s, o);
                c += __shfl_down_sync(0xffffffffu, c, o);
            }
            if (lane == 0) {
                out[0] = s / (float)c;
                g_done = 0;   // reset for next graph replay
            }
        }
    }
}

extern "C" void kernel_launch(void* const* d_in, const int* in_sizes, int n_in,
                              void* d_out, int out_size) {
    const float* sim = (const float*)d_in[0];
    const float* gt  = (const float*)d_in[1];
    float* out       = (float*)d_out;

    sce_fused_kernel<<<NBLOCKS, TPB>>>(sim, gt, out);
}